// round 12
// baseline (speedup 1.0000x reference)
#include <cuda_runtime.h>
#include <cuda_bf16.h>
#include <cstdint>

// ============================================================================
// Fused dopri5 neural-ODE via mma.sync bf16 (sm_103-safe HMMA path).
// fp32 = bf16 hi/lo split, 3 products. Grid=128 CTAs x 32 rows, 16 warps.
// R11: K-split warp layout (8 n32-strips x 2 k-halves) halves A ldsm traffic;
// cross-warp fp32 partial-sum exchange via smem; W ring depth 3.
// ============================================================================

#define THREADS   512
#define NWARP     16
#define NSTEPS    40
#define DIM       256
#define BROWS     4096
#define M_CTA     32
#define NCTA      (BROWS / M_CTA)        // 128
#define NGEMM     (NSTEPS * 6 * 2)       // 480
#define NSUB      (NGEMM * 8)            // 3840 k32-subchunks

#define LDA       264                    // A row stride (elements)
#define ABUF_B    (M_CTA * LDA * 2 * 2)  // 33792 (hi+lo planes)
#define A_LO      (M_CTA * LDA * 2)      // 16896
#define RED_OFF   (2 * ABUF_B)           // 67584
#define RED_WARP  2048                   // 16 floats/thread exchange
#define W_OFF     (RED_OFF + NWARP * RED_WARP)  // 100352
#define WPITCH    80                     // slice row pitch (hi@0, lo@32)
#define WSLOT     (32 * WPITCH)          // 2560
#define WRING     3
#define WWARP     (WRING * WSLOT)        // 7680
#define SMEM_BYTES (W_OFF + NWARP * WWARP) // 223232

#define FRAG_CTA  (M_CTA * DIM)          // 8192 floats per CTA

__device__ __nv_bfloat16 g_wimg[2 * 2 * 256 * 256]; // [wi][half][n][k]
__device__ float g_k[4][BROWS * DIM];               // k1..k4, fragment layout

__constant__ float c_cur[6] = {
    (float)(0.025 * 0.2), (float)(0.025 * 9.0 / 40.0), (float)(0.025 * 32.0 / 9.0),
    (float)(0.025 * -212.0 / 729.0), (float)(0.025 * -5103.0 / 18656.0),
    (float)(0.025 * 11.0 / 84.0)};
__constant__ float c_slot[5][4] = {
    {0.f, 0.f, 0.f, 0.f},
    {(float)(0.025 * 3.0 / 40.0), 0.f, 0.f, 0.f},
    {(float)(0.025 * 44.0 / 45.0), (float)(0.025 * -56.0 / 15.0), 0.f, 0.f},
    {(float)(0.025 * 19372.0 / 6561.0), (float)(0.025 * -25360.0 / 2187.0),
     (float)(0.025 * 64448.0 / 6561.0), 0.f},
    {(float)(0.025 * 9017.0 / 3168.0), (float)(0.025 * -355.0 / 33.0),
     (float)(0.025 * 46732.0 / 5247.0), (float)(0.025 * 49.0 / 176.0)}};
__constant__ float c_b[6] = {
    (float)(0.025 * 35.0 / 384.0), 0.f, (float)(0.025 * 500.0 / 1113.0),
    (float)(0.025 * 125.0 / 192.0), (float)(0.025 * -2187.0 / 6784.0), 0.f};

__device__ __forceinline__ uint32_t smem_u32(const void* p) {
    uint32_t a;
    asm("{ .reg .u64 t; cvta.to.shared.u64 t, %1; cvt.u32.u64 %0, t; }" : "=r"(a) : "l"(p));
    return a;
}
__device__ __forceinline__ void cp_async16(uint32_t sdst, const void* gsrc) {
    asm volatile("cp.async.cg.shared.global [%0], [%1], 16;\n" ::"r"(sdst), "l"(gsrc));
}
__device__ __forceinline__ void cp_commit() { asm volatile("cp.async.commit_group;\n" ::: "memory"); }
__device__ __forceinline__ void cp_wait2()  { asm volatile("cp.async.wait_group 2;\n" ::: "memory"); }
__device__ __forceinline__ void cp_wait0()  { asm volatile("cp.async.wait_group 0;\n" ::: "memory"); }

__device__ __forceinline__ void ldsm_x4(uint32_t* r, uint32_t addr) {
    asm volatile("ldmatrix.sync.aligned.m8n8.x4.shared.b16 {%0,%1,%2,%3}, [%4];"
                 : "=r"(r[0]), "=r"(r[1]), "=r"(r[2]), "=r"(r[3]) : "r"(addr));
}
__device__ __forceinline__ void mma_bf16(float* c, const uint32_t* a, const uint32_t* b) {
    asm volatile("mma.sync.aligned.m16n8k16.row.col.f32.bf16.bf16.f32 "
                 "{%0,%1,%2,%3}, {%4,%5,%6,%7}, {%8,%9}, {%0,%1,%2,%3};"
                 : "+f"(c[0]), "+f"(c[1]), "+f"(c[2]), "+f"(c[3])
                 : "r"(a[0]), "r"(a[1]), "r"(a[2]), "r"(a[3]), "r"(b[0]), "r"(b[1]));
}

__device__ __forceinline__ float tanh_f(float x) {
    float ax = fabsf(x);
    float e  = __expf(2.0f * ax);
    float r  = __fdividef(2.0f, e + 1.0f);
    return copysignf(1.0f - r, x);
}
__device__ __forceinline__ uint32_t bpack(float a, float b) {
    __nv_bfloat162 h = __floats2bfloat162_rn(a, b);
    return *(uint32_t*)&h;
}
__device__ __forceinline__ void writeA(uint32_t sb, int buf, int row, int col,
                                       float a, float b) {
    float ah = __bfloat162float(__float2bfloat16(a));
    float bh = __bfloat162float(__float2bfloat16(b));
    uint32_t off = sb + (uint32_t)buf * ABUF_B + (uint32_t)(row * LDA + col) * 2;
    asm volatile("st.shared.b32 [%0], %1;" :: "r"(off), "r"(bpack(ah, bh)) : "memory");
    asm volatile("st.shared.b32 [%0], %1;" :: "r"(off + A_LO), "r"(bpack(a - ah, b - bh)) : "memory");
}

__global__ void prep_kernel(const float* __restrict__ W1, const float* __restrict__ W2) {
    int e = blockIdx.x * blockDim.x + threadIdx.x;   // k*256 + n
    int k = e >> 8, n = e & 255;
#pragma unroll
    for (int wi = 0; wi < 2; wi++) {
        float v = (wi ? W2 : W1)[k * 256 + n];
        __nv_bfloat16 hi = __float2bfloat16(v);
        float lo = v - __bfloat162float(hi);
        g_wimg[((wi * 2 + 0) << 16) + n * 256 + k] = hi;
        g_wimg[((wi * 2 + 1) << 16) + n * 256 + k] = __float2bfloat16(lo);
    }
}

// warp (kh, ns): load its n32 rows x its k16 half of subchunk ci (hi+lo = 2KB)
__device__ __forceinline__ void load_slice(uint32_t sb, int ci, int warp, int lane) {
    const int g = ci >> 3, wi = g & 1, sub = ci & 7;
    const int kh = warp >> 3, ns = warp & 7;
    const uint32_t dst = sb + W_OFF + (uint32_t)warp * WWARP + (uint32_t)(ci % WRING) * WSLOT;
#pragma unroll
    for (int i = 0; i < 4; i++) {
        int idx = lane + i * 32;                     // 0..127
        int plane = idx >> 6, r = (idx >> 1) & 31, seg = idx & 1;
        const __nv_bfloat16* src = g_wimg +
            (((wi * 2 + plane) << 16) + (ns * 32 + r) * 256 + sub * 32 + kh * 16 + seg * 8);
        cp_async16(dst + r * WPITCH + plane * 32 + seg * 16, src);
    }
    cp_commit();
}

__global__ void __launch_bounds__(THREADS, 1)
ode_hmma_kernel(const float* __restrict__ x0, float* __restrict__ out) {
    extern __shared__ __align__(16) char smem[];
    const uint32_t sb = smem_u32(smem);
    const int tid = threadIdx.x, warp = tid >> 5, lane = tid & 31;
    const int quad = lane >> 3, lrow = lane & 7;
    const int kh = warp >> 3, ns = warp & 7;

    const int a_row  = lrow + ((quad & 1) << 3);
    const int a_col8 = (quad >> 1) << 3;
    const int b_row  = lrow + ((quad >> 1) << 3);
    const int b_kadd = (quad & 1) << 3;

    const int erow = lane >> 2;                      // 0..7
    const int orow = kh * 16 + erow;                 // owned rows: orow, orow+8
    const int ecol = ns * 32 + 2 * (lane & 3);       // + ni*8, ni<4
    const int fbase = blockIdx.x * FRAG_CTA + warp * 512 + lane * 4;
    const int growb = blockIdx.x * M_CTA;
    const uint32_t red_me = sb + RED_OFF + (uint32_t)warp * RED_WARP + (uint32_t)lane * 16;
    const uint32_t red_pa = sb + RED_OFF + (uint32_t)(warp ^ 8) * RED_WARP + (uint32_t)lane * 16;

    float4 xreg[4], xacc[4];

    // ---- init: x0 -> x regs (own quarter) and A buffer 0 ----
#pragma unroll
    for (int ni = 0; ni < 4; ni++) {
        int col = ecol + ni * 8;
        float2 v01 = *(const float2*)&x0[(growb + orow) * DIM + col];
        float2 v23 = *(const float2*)&x0[(growb + orow + 8) * DIM + col];
        xreg[ni] = make_float4(v01.x, v01.y, v23.x, v23.y);
        writeA(sb, 0, orow, col, v01.x, v01.y);
        writeA(sb, 0, orow + 8, col, v23.x, v23.y);
    }

#pragma unroll
    for (int i = 0; i < 3; i++) load_slice(sb, i, warp, lane);

    __syncthreads();

    float acc[2][4][4];
#pragma unroll 1
    for (int g = 0; g < NGEMM; g++) {
        const int s = (g >> 1) % 6, j = g & 1;
        const uint32_t abase = sb + (uint32_t)(g & 1) * ABUF_B;
#pragma unroll
        for (int mi = 0; mi < 2; mi++)
#pragma unroll
            for (int ni = 0; ni < 4; ni++)
#pragma unroll
                for (int c = 0; c < 4; c++) acc[mi][ni][c] = 0.0f;

#pragma unroll 1
        for (int sub = 0; sub < 8; sub++) {
            const int ci = g * 8 + sub;
            if (ci + 3 < NSUB) cp_wait2(); else cp_wait0();
            __syncwarp();
            const uint32_t wsl = sb + W_OFF + (uint32_t)warp * WWARP +
                                 (uint32_t)(ci % WRING) * WSLOT;
            const int kg = sub * 32 + kh * 16;       // this warp's k16 half
            uint32_t ahi[2][4], alo[2][4], bhi[8], blo[8];
#pragma unroll
            for (int mi = 0; mi < 2; mi++) {
                uint32_t ao = abase + (uint32_t)(((mi * 16 + a_row) * LDA + kg + a_col8) * 2);
                ldsm_x4(ahi[mi], ao);
                ldsm_x4(alo[mi], ao + A_LO);
            }
#pragma unroll
            for (int np = 0; np < 2; np++) {
                uint32_t bo = wsl + (uint32_t)((np * 16 + b_row) * WPITCH + b_kadd * 2);
                ldsm_x4(&bhi[np * 4], bo);
                ldsm_x4(&blo[np * 4], bo + 32);
            }
#pragma unroll
            for (int mi = 0; mi < 2; mi++)
#pragma unroll
                for (int ni = 0; ni < 4; ni++) {
                    mma_bf16(acc[mi][ni], ahi[mi], &bhi[ni * 2]);  // hi*hi
                    mma_bf16(acc[mi][ni], alo[mi], &bhi[ni * 2]);  // lo*hi
                    mma_bf16(acc[mi][ni], ahi[mi], &blo[ni * 2]);  // hi*lo
                }
            if (ci + 3 < NSUB) load_slice(sb, ci + 3, warp, lane);
        }

        // ---- cross-warp k-reduction: send non-owned mi, receive own mi ----
        {
            const int omi = 1 - kh;
#pragma unroll
            for (int f = 0; f < 4; f++) {
                float4 v = make_float4(acc[omi][f][0], acc[omi][f][1],
                                       acc[omi][f][2], acc[omi][f][3]);
                asm volatile("st.shared.v4.b32 [%0], {%1,%2,%3,%4};"
                             :: "r"(red_me + f * 512),
                                "r"(__float_as_uint(v.x)), "r"(__float_as_uint(v.y)),
                                "r"(__float_as_uint(v.z)), "r"(__float_as_uint(v.w))
                             : "memory");
            }
        }
        __syncthreads();
#pragma unroll
        for (int f = 0; f < 4; f++) {
            uint32_t r0, r1, r2, r3;
            asm volatile("ld.shared.v4.b32 {%0,%1,%2,%3}, [%4];"
                         : "=r"(r0), "=r"(r1), "=r"(r2), "=r"(r3)
                         : "r"(red_pa + f * 512));
            acc[kh][f][0] += __uint_as_float(r0);
            acc[kh][f][1] += __uint_as_float(r1);
            acc[kh][f][2] += __uint_as_float(r2);
            acc[kh][f][3] += __uint_as_float(r3);
        }

        // ---- epilogue on own quarter (rows orow/orow+8, n32 strip) ----
        const int nbuf = (g + 1) & 1;
        if (j == 0) {                      // h = tanh(x@W1)
#pragma unroll
            for (int ni = 0; ni < 4; ni++) {
                float* a = acc[kh][ni];
                int col = ecol + ni * 8;
                writeA(sb, nbuf, orow, col, tanh_f(a[0]), tanh_f(a[1]));
                writeA(sb, nbuf, orow + 8, col, tanh_f(a[2]), tanh_f(a[3]));
            }
        } else {                           // k_{s+1} = h@W2; RK update
            const bool fin = (s == 5);
            const float cc = c_cur[s];
            const float cb = c_b[s];
#pragma unroll
            for (int ni = 0; ni < 4; ni++) {
                float* a = acc[kh][ni];
                const int fi = fbase + ni * 128;
                float4 kc = make_float4(a[0], a[1], a[2], a[3]);
                if (s <= 3) *(float4*)&g_k[s][fi] = kc;
                float4 xv = xreg[ni];
                if (s == 0) {
                    xacc[ni] = make_float4(fmaf(cb, kc.x, xv.x), fmaf(cb, kc.y, xv.y),
                                           fmaf(cb, kc.z, xv.z), fmaf(cb, kc.w, xv.w));
                } else if (cb != 0.0f) {
                    float4 t = xacc[ni];
                    xacc[ni] = make_float4(fmaf(cb, kc.x, t.x), fmaf(cb, kc.y, t.y),
                                           fmaf(cb, kc.z, t.z), fmaf(cb, kc.w, t.w));
                }
                float4 na;
                if (!fin) {
                    na = make_float4(fmaf(cc, kc.x, xv.x), fmaf(cc, kc.y, xv.y),
                                     fmaf(cc, kc.z, xv.z), fmaf(cc, kc.w, xv.w));
                    float4 kv[4];
#pragma unroll
                    for (int sl = 0; sl < 4; sl++)
                        if (sl < s) kv[sl] = *(const float4*)&g_k[sl][fi];
#pragma unroll
                    for (int sl = 0; sl < 4; sl++)
                        if (sl < s) {
                            float cf = c_slot[s][sl];
                            na.x = fmaf(cf, kv[sl].x, na.x);
                            na.y = fmaf(cf, kv[sl].y, na.y);
                            na.z = fmaf(cf, kv[sl].z, na.z);
                            na.w = fmaf(cf, kv[sl].w, na.w);
                        }
                } else {
                    float4 t = xacc[ni];
                    na = make_float4(fmaf(cc, kc.x, t.x), fmaf(cc, kc.y, t.y),
                                     fmaf(cc, kc.z, t.z), fmaf(cc, kc.w, t.w));
                    xreg[ni] = na;
                }
                int col = ecol + ni * 8;
                if (g == NGEMM - 1) {
                    *(float2*)&out[(growb + orow) * DIM + col] = make_float2(na.x, na.y);
                    *(float2*)&out[(growb + orow + 8) * DIM + col] = make_float2(na.z, na.w);
                } else {
                    writeA(sb, nbuf, orow, col, na.x, na.y);
                    writeA(sb, nbuf, orow + 8, col, na.z, na.w);
                }
            }
        }
        __syncthreads();   // publish A buffer (g+1)&1 and free red buffer
    }
}

extern "C" void kernel_launch(void* const* d_in, const int* in_sizes, int n_in,
                              void* d_out, int out_size) {
    (void)in_sizes; (void)n_in; (void)out_size;
    const float* x0 = (const float*)d_in[0];
    const float* W1 = (const float*)d_in[1];
    const float* W2 = (const float*)d_in[2];
    float* out = (float*)d_out;

    prep_kernel<<<256, 256>>>(W1, W2);
    cudaFuncSetAttribute(ode_hmma_kernel,
                         cudaFuncAttributeMaxDynamicSharedMemorySize, SMEM_BYTES);
    ode_hmma_kernel<<<NCTA, THREADS, SMEM_BYTES>>>(x0, out);
}

// round 13
// speedup vs baseline: 2.1681x; 2.1681x over previous
#include <cuda_runtime.h>
#include <cuda_bf16.h>
#include <cstdint>

// ============================================================================
// Fused dopri5 neural-ODE via mma.sync bf16 (sm_103-safe HMMA path).
// fp32 = bf16 hi/lo split, 3 products. Grid=128 CTAs x 32 rows, 16 warps.
// R12 (from R10 base; R11 k-split reverted): W lives in GLOBAL memory in
// mma-FRAGMENT order (prep kernel) and is loaded straight into registers via
// coalesced ld.global.v4 with 1-subchunk prefetch. B-ldsm and W cp.async are
// gone from the smem port (128KB -> 64KB per subchunk). xacc -> smem.
// ============================================================================

#define THREADS   512
#define NWARP     16
#define NSTEPS    40
#define DIM       256
#define BROWS     4096
#define M_CTA     32
#define NCTA      (BROWS / M_CTA)        // 128
#define NGEMM     (NSTEPS * 6 * 2)       // 480
#define NSUB      (NGEMM * 8)            // 3840 k32-subchunks

#define LDA       264                    // A row stride (elements)
#define ABUF_B    (M_CTA * LDA * 2 * 2)  // 33792 (hi+lo planes)
#define A_LO      (M_CTA * LDA * 2)      // 16896
#define XACC_OFF  (2 * ABUF_B)           // 67584
#define SMEM_BYTES (XACC_OFF + 4 * 512 * 16)  // + xacc [4][512]*16B = 100352

#define FRAG_CTA  (M_CTA * DIM)          // 8192 floats per CTA

// W fragment image: uint32[131072] = 512KB, L2-resident.
// index = ((((wi*16+ns)*8+sub)*4 + (kq*2+plane))*32 + lane)*4 + r
__device__ uint32_t g_wfrag[131072];
__device__ float g_k[4][BROWS * DIM];    // k1..k4, fragment layout

__constant__ float c_cur[6] = {
    (float)(0.025 * 0.2), (float)(0.025 * 9.0 / 40.0), (float)(0.025 * 32.0 / 9.0),
    (float)(0.025 * -212.0 / 729.0), (float)(0.025 * -5103.0 / 18656.0),
    (float)(0.025 * 11.0 / 84.0)};
__constant__ float c_slot[5][4] = {
    {0.f, 0.f, 0.f, 0.f},
    {(float)(0.025 * 3.0 / 40.0), 0.f, 0.f, 0.f},
    {(float)(0.025 * 44.0 / 45.0), (float)(0.025 * -56.0 / 15.0), 0.f, 0.f},
    {(float)(0.025 * 19372.0 / 6561.0), (float)(0.025 * -25360.0 / 2187.0),
     (float)(0.025 * 64448.0 / 6561.0), 0.f},
    {(float)(0.025 * 9017.0 / 3168.0), (float)(0.025 * -355.0 / 33.0),
     (float)(0.025 * 46732.0 / 5247.0), (float)(0.025 * 49.0 / 176.0)}};
__constant__ float c_b[6] = {
    (float)(0.025 * 35.0 / 384.0), 0.f, (float)(0.025 * 500.0 / 1113.0),
    (float)(0.025 * 125.0 / 192.0), (float)(0.025 * -2187.0 / 6784.0), 0.f};

__device__ __forceinline__ uint32_t smem_u32(const void* p) {
    uint32_t a;
    asm("{ .reg .u64 t; cvta.to.shared.u64 t, %1; cvt.u32.u64 %0, t; }" : "=r"(a) : "l"(p));
    return a;
}
__device__ __forceinline__ void ldsm_x4(uint32_t* r, uint32_t addr) {
    asm volatile("ldmatrix.sync.aligned.m8n8.x4.shared.b16 {%0,%1,%2,%3}, [%4];"
                 : "=r"(r[0]), "=r"(r[1]), "=r"(r[2]), "=r"(r[3]) : "r"(addr));
}
__device__ __forceinline__ void mma_bf16(float* c, const uint32_t* a, const uint32_t* b) {
    asm volatile("mma.sync.aligned.m16n8k16.row.col.f32.bf16.bf16.f32 "
                 "{%0,%1,%2,%3}, {%4,%5,%6,%7}, {%8,%9}, {%0,%1,%2,%3};"
                 : "+f"(c[0]), "+f"(c[1]), "+f"(c[2]), "+f"(c[3])
                 : "r"(a[0]), "r"(a[1]), "r"(a[2]), "r"(a[3]), "r"(b[0]), "r"(b[1]));
}

__device__ __forceinline__ float tanh_f(float x) {
    float ax = fabsf(x);
    float e  = __expf(2.0f * ax);
    float r  = __fdividef(2.0f, e + 1.0f);
    return copysignf(1.0f - r, x);
}
__device__ __forceinline__ uint32_t bpack(float a, float b) {
    __nv_bfloat162 h = __floats2bfloat162_rn(a, b);
    return *(uint32_t*)&h;
}
__device__ __forceinline__ void writeA(uint32_t sb, int buf, int row, int col,
                                       float a, float b) {
    float ah = __bfloat162float(__float2bfloat16(a));
    float bh = __bfloat162float(__float2bfloat16(b));
    uint32_t off = sb + (uint32_t)buf * ABUF_B + (uint32_t)(row * LDA + col) * 2;
    asm volatile("st.shared.b32 [%0], %1;" :: "r"(off), "r"(bpack(ah, bh)) : "memory");
    asm volatile("st.shared.b32 [%0], %1;" :: "r"(off + A_LO), "r"(bpack(a - ah, b - bh)) : "memory");
}
__device__ __forceinline__ void sts_f4(uint32_t addr, float4 v) {
    asm volatile("st.shared.v4.b32 [%0], {%1,%2,%3,%4};"
                 :: "r"(addr), "r"(__float_as_uint(v.x)), "r"(__float_as_uint(v.y)),
                    "r"(__float_as_uint(v.z)), "r"(__float_as_uint(v.w)) : "memory");
}
__device__ __forceinline__ float4 lds_f4(uint32_t addr) {
    uint32_t a, b, c, d;
    asm volatile("ld.shared.v4.b32 {%0,%1,%2,%3}, [%4];"
                 : "=r"(a), "=r"(b), "=r"(c), "=r"(d) : "r"(addr));
    return make_float4(__uint_as_float(a), __uint_as_float(b),
                       __uint_as_float(c), __uint_as_float(d));
}

// ---------------------------------------------------------------------------
// prep: W -> fragment-order image. For lane l, reg r of the m16n8k16 B frag:
//   b-pair = { B[n][k], B[n][k+1] },  n = ns*16 + (r>>1)*8 + l/4,
//   k = sub*32 + kq*16 + (r&1)*8 + 2*(l&3).   B[n][k] = W[k][n]. hi/lo planes.
// ---------------------------------------------------------------------------
__global__ void prep_kernel(const float* __restrict__ W1, const float* __restrict__ W2) {
    int i = blockIdx.x * blockDim.x + threadIdx.x;   // 0..131071
    int r = i & 3, lane = (i >> 2) & 31, plane = (i >> 7) & 1;
    int kq = (i >> 8) & 1, sub = (i >> 9) & 7, ns = (i >> 12) & 15, wi = (i >> 16) & 1;
    int n = ns * 16 + (r >> 1) * 8 + (lane >> 2);
    int k = sub * 32 + kq * 16 + (r & 1) * 8 + 2 * (lane & 3);
    const float* W = wi ? W2 : W1;
    float v0 = W[k * 256 + n], v1 = W[(k + 1) * 256 + n];
    __nv_bfloat16 h0 = __float2bfloat16(v0), h1 = __float2bfloat16(v1);
    uint32_t outv;
    if (plane == 0) {
        outv = ((uint32_t)__bfloat16_as_ushort(h1) << 16) | __bfloat16_as_ushort(h0);
    } else {
        __nv_bfloat16 l0 = __float2bfloat16(v0 - __bfloat162float(h0));
        __nv_bfloat16 l1 = __float2bfloat16(v1 - __bfloat162float(h1));
        outv = ((uint32_t)__bfloat16_as_ushort(l1) << 16) | __bfloat16_as_ushort(l0);
    }
    g_wfrag[i] = outv;
}

// load this warp's B frags (kq0hi,kq0lo,kq1hi,kq1lo = 4x uint4) for (wi, sub)
__device__ __forceinline__ void ldw(int wi, int sub, int warp, int lane, uint32_t* dst) {
    const uint4* p = (const uint4*)g_wfrag +
                     (((wi * 16 + warp) * 8 + sub) * 4) * 32 + lane;
    uint4 t0 = p[0], t1 = p[32], t2 = p[64], t3 = p[96];
    dst[0] = t0.x; dst[1] = t0.y; dst[2]  = t0.z; dst[3]  = t0.w;  // kq0 hi
    dst[4] = t1.x; dst[5] = t1.y; dst[6]  = t1.z; dst[7]  = t1.w;  // kq0 lo
    dst[8] = t2.x; dst[9] = t2.y; dst[10] = t2.z; dst[11] = t2.w;  // kq1 hi
    dst[12] = t3.x; dst[13] = t3.y; dst[14] = t3.z; dst[15] = t3.w; // kq1 lo
}

__global__ void __launch_bounds__(THREADS, 1)
ode_hmma_kernel(const float* __restrict__ x0, float* __restrict__ out) {
    extern __shared__ __align__(16) char smem[];
    const uint32_t sb = smem_u32(smem);
    const int tid = threadIdx.x, warp = tid >> 5, lane = tid & 31;
    const int quad = lane >> 3, lrow = lane & 7;

    const int a_row  = lrow + ((quad & 1) << 3);
    const int a_col8 = (quad >> 1) << 3;

    const int erow = lane >> 2;
    const int ecol = warp * 16 + 2 * (lane & 3);     // + ni*8
    const int fbase = blockIdx.x * FRAG_CTA + warp * 512 + lane * 4;
    const int growb = blockIdx.x * M_CTA;
    const uint32_t xab = sb + XACC_OFF + (uint32_t)(warp * 32 + lane) * 16;  // + idx*8192

    float4 xreg[4];

    // ---- init: x0 -> x regs and A buffer 0 ----
#pragma unroll
    for (int mi = 0; mi < 2; mi++)
#pragma unroll
        for (int ni = 0; ni < 2; ni++) {
            int row = mi * 16 + erow, col = ecol + ni * 8;
            float2 v01 = *(const float2*)&x0[(growb + row) * DIM + col];
            float2 v23 = *(const float2*)&x0[(growb + row + 8) * DIM + col];
            xreg[mi * 2 + ni] = make_float4(v01.x, v01.y, v23.x, v23.y);
            writeA(sb, 0, row, col, v01.x, v01.y);
            writeA(sb, 0, row + 8, col, v23.x, v23.y);
        }

    uint32_t bw[2][16];
    ldw(0, 0, warp, lane, bw[0]);      // prefetch subchunk 0 (W1)

    __syncthreads();

    float accA[2][2][4], accB[2][2][4];
#pragma unroll 1
    for (int g = 0; g < NGEMM; g++) {
        const int s = (g >> 1) % 6, j = g & 1;
        const uint32_t abase = sb + (uint32_t)(g & 1) * ABUF_B;
#pragma unroll
        for (int mi = 0; mi < 2; mi++)
#pragma unroll
            for (int ni = 0; ni < 2; ni++)
#pragma unroll
                for (int c = 0; c < 4; c++) {
                    accA[mi][ni][c] = 0.0f;
                    accB[mi][ni][c] = 0.0f;
                }

#pragma unroll 2
        for (int sub = 0; sub < 8; sub++) {
            const int ci = g * 8 + sub;
            // prefetch next subchunk's B frags into the other register buffer
            if (ci + 1 < NSUB) {
                const int cn = ci + 1;
                ldw(((cn >> 3) & 1), cn & 7, warp, lane, bw[cn & 1]);
            }
            const uint32_t* bb = bw[ci & 1];
#pragma unroll
            for (int kq = 0; kq < 2; kq++) {
                const uint32_t* bhi = bb + kq * 8;
                const uint32_t* blo = bhi + 4;
                const int kg = sub * 32 + kq * 16;
#pragma unroll
                for (int mi = 0; mi < 2; mi++) {
                    uint32_t ahi[4], alo[4];
                    uint32_t ao = abase + (uint32_t)(((mi * 16 + a_row) * LDA + kg + a_col8) * 2);
                    ldsm_x4(ahi, ao);
                    ldsm_x4(alo, ao + A_LO);
#pragma unroll
                    for (int ni = 0; ni < 2; ni++) {
                        mma_bf16(accA[mi][ni], ahi, &bhi[ni * 2]);  // hi*hi
                        mma_bf16(accB[mi][ni], alo, &bhi[ni * 2]);  // lo*hi
                        mma_bf16(accB[mi][ni], ahi, &blo[ni * 2]);  // hi*lo
                    }
                }
            }
        }

        // ---- epilogue -> A buffer (g+1)&1 ----
        const int nbuf = (g + 1) & 1;
        if (j == 0) {                      // h = tanh(x@W1)
#pragma unroll
            for (int mi = 0; mi < 2; mi++)
#pragma unroll
                for (int ni = 0; ni < 2; ni++) {
                    float a0 = accA[mi][ni][0] + accB[mi][ni][0];
                    float a1 = accA[mi][ni][1] + accB[mi][ni][1];
                    float a2 = accA[mi][ni][2] + accB[mi][ni][2];
                    float a3 = accA[mi][ni][3] + accB[mi][ni][3];
                    int row = mi * 16 + erow, col = ecol + ni * 8;
                    writeA(sb, nbuf, row, col, tanh_f(a0), tanh_f(a1));
                    writeA(sb, nbuf, row + 8, col, tanh_f(a2), tanh_f(a3));
                }
        } else {                           // k_{s+1} = h@W2; RK update
            const bool fin = (s == 5);
            const float cc = c_cur[s];
            const float cb = c_b[s];
#pragma unroll
            for (int mi = 0; mi < 2; mi++)
#pragma unroll
                for (int ni = 0; ni < 2; ni++) {
                    const int idx = mi * 2 + ni;
                    const int fi = fbase + idx * 128;
                    const uint32_t xaddr = xab + (uint32_t)idx * 8192;
                    float4 kc = make_float4(accA[mi][ni][0] + accB[mi][ni][0],
                                            accA[mi][ni][1] + accB[mi][ni][1],
                                            accA[mi][ni][2] + accB[mi][ni][2],
                                            accA[mi][ni][3] + accB[mi][ni][3]);
                    if (s <= 3) *(float4*)&g_k[s][fi] = kc;
                    float4 xv = xreg[idx];
                    if (s == 0) {
                        sts_f4(xaddr, make_float4(fmaf(cb, kc.x, xv.x), fmaf(cb, kc.y, xv.y),
                                                  fmaf(cb, kc.z, xv.z), fmaf(cb, kc.w, xv.w)));
                    } else if (cb != 0.0f) {
                        float4 t = lds_f4(xaddr);
                        sts_f4(xaddr, make_float4(fmaf(cb, kc.x, t.x), fmaf(cb, kc.y, t.y),
                                                  fmaf(cb, kc.z, t.z), fmaf(cb, kc.w, t.w)));
                    }
                    float4 na;
                    if (!fin) {            // y_{s+2} = x + cc*k_cur + sum_{sl<s} slots
                        na = make_float4(fmaf(cc, kc.x, xv.x), fmaf(cc, kc.y, xv.y),
                                         fmaf(cc, kc.z, xv.z), fmaf(cc, kc.w, xv.w));
                        float4 kv[4];
#pragma unroll
                        for (int sl = 0; sl < 4; sl++)
                            if (sl < s) kv[sl] = *(const float4*)&g_k[sl][fi];
#pragma unroll
                        for (int sl = 0; sl < 4; sl++)
                            if (sl < s) {
                                float cf = c_slot[s][sl];
                                na.x = fmaf(cf, kv[sl].x, na.x);
                                na.y = fmaf(cf, kv[sl].y, na.y);
                                na.z = fmaf(cf, kv[sl].z, na.z);
                                na.w = fmaf(cf, kv[sl].w, na.w);
                            }
                    } else {               // new x = xacc + h*b6*k6
                        float4 t = lds_f4(xaddr);
                        na = make_float4(fmaf(cc, kc.x, t.x), fmaf(cc, kc.y, t.y),
                                         fmaf(cc, kc.z, t.z), fmaf(cc, kc.w, t.w));
                        xreg[idx] = na;
                    }
                    int row = mi * 16 + erow, col = ecol + ni * 8;
                    if (g == NGEMM - 1) {
                        *(float2*)&out[(growb + row) * DIM + col] = make_float2(na.x, na.y);
                        *(float2*)&out[(growb + row + 8) * DIM + col] = make_float2(na.z, na.w);
                    } else {
                        writeA(sb, nbuf, row, col, na.x, na.y);
                        writeA(sb, nbuf, row + 8, col, na.z, na.w);
                    }
                }
        }
        __syncthreads();   // publish A buffer (g+1)&1
    }
}

extern "C" void kernel_launch(void* const* d_in, const int* in_sizes, int n_in,
                              void* d_out, int out_size) {
    (void)in_sizes; (void)n_in; (void)out_size;
    const float* x0 = (const float*)d_in[0];
    const float* W1 = (const float*)d_in[1];
    const float* W2 = (const float*)d_in[2];
    float* out = (float*)d_out;

    prep_kernel<<<512, 256>>>(W1, W2);
    cudaFuncSetAttribute(ode_hmma_kernel,
                         cudaFuncAttributeMaxDynamicSharedMemorySize, SMEM_BYTES);
    ode_hmma_kernel<<<NCTA, THREADS, SMEM_BYTES>>>(x0, out);
}

// round 14
// speedup vs baseline: 2.1724x; 1.0020x over previous
#include <cuda_runtime.h>
#include <cuda_bf16.h>
#include <cstdint>

// ============================================================================
// Fused dopri5 neural-ODE via mma.sync bf16 (sm_103-safe HMMA path).
// fp32 = bf16 hi/lo split, 3 products.
// R13: 256 CTAs x 16 rows, 256 threads, 2 CTAs/SM (occupancy x2).
// Warp = n32 strip x m16. W in GLOBAL fragment order -> registers (per-kq-step
// double buffer). A via ldsm from double-buffered smem. xacc in smem.
// ============================================================================

#define THREADS   256
#define NWARP     8
#define NSTEPS    40
#define DIM       256
#define BROWS     4096
#define M_CTA     16
#define NCTA      (BROWS / M_CTA)        // 256
#define NGEMM     (NSTEPS * 6 * 2)       // 480
#define NKSTEP    (NGEMM * 16)           // 7680 k16-steps

#define LDA       264                    // A row stride (elements)
#define ABUF_B    (M_CTA * LDA * 2 * 2)  // 16896 (hi+lo planes)
#define A_LO      (M_CTA * LDA * 2)      // 8448
#define XACC_OFF  (2 * ABUF_B)           // 33792
#define SMEM_BYTES (XACC_OFF + 4 * THREADS * 16)  // 50176

#define FRAG_CTA  (M_CTA * DIM)          // 4096 floats per CTA

// W fragment image (512KB, L2-resident), uint4 granularity:
// combo = ((((wi*8+ns)*8+sub)*2+kq)*2+plane), 64 uint4 per combo:
//   [h(2)][lane(32)] -> uint4 = regs (h*4 .. h*4+3) of that lane.
__device__ uint32_t g_wfrag[131072];
__device__ float g_k[4][BROWS * DIM];    // k1..k4, fragment layout

__constant__ float c_cur[6] = {
    (float)(0.025 * 0.2), (float)(0.025 * 9.0 / 40.0), (float)(0.025 * 32.0 / 9.0),
    (float)(0.025 * -212.0 / 729.0), (float)(0.025 * -5103.0 / 18656.0),
    (float)(0.025 * 11.0 / 84.0)};
__constant__ float c_slot[5][4] = {
    {0.f, 0.f, 0.f, 0.f},
    {(float)(0.025 * 3.0 / 40.0), 0.f, 0.f, 0.f},
    {(float)(0.025 * 44.0 / 45.0), (float)(0.025 * -56.0 / 15.0), 0.f, 0.f},
    {(float)(0.025 * 19372.0 / 6561.0), (float)(0.025 * -25360.0 / 2187.0),
     (float)(0.025 * 64448.0 / 6561.0), 0.f},
    {(float)(0.025 * 9017.0 / 3168.0), (float)(0.025 * -355.0 / 33.0),
     (float)(0.025 * 46732.0 / 5247.0), (float)(0.025 * 49.0 / 176.0)}};
__constant__ float c_b[6] = {
    (float)(0.025 * 35.0 / 384.0), 0.f, (float)(0.025 * 500.0 / 1113.0),
    (float)(0.025 * 125.0 / 192.0), (float)(0.025 * -2187.0 / 6784.0), 0.f};

__device__ __forceinline__ uint32_t smem_u32(const void* p) {
    uint32_t a;
    asm("{ .reg .u64 t; cvta.to.shared.u64 t, %1; cvt.u32.u64 %0, t; }" : "=r"(a) : "l"(p));
    return a;
}
__device__ __forceinline__ void ldsm_x4(uint32_t* r, uint32_t addr) {
    asm volatile("ldmatrix.sync.aligned.m8n8.x4.shared.b16 {%0,%1,%2,%3}, [%4];"
                 : "=r"(r[0]), "=r"(r[1]), "=r"(r[2]), "=r"(r[3]) : "r"(addr));
}
__device__ __forceinline__ void mma_bf16(float* c, const uint32_t* a, const uint32_t* b) {
    asm volatile("mma.sync.aligned.m16n8k16.row.col.f32.bf16.bf16.f32 "
                 "{%0,%1,%2,%3}, {%4,%5,%6,%7}, {%8,%9}, {%0,%1,%2,%3};"
                 : "+f"(c[0]), "+f"(c[1]), "+f"(c[2]), "+f"(c[3])
                 : "r"(a[0]), "r"(a[1]), "r"(a[2]), "r"(a[3]), "r"(b[0]), "r"(b[1]));
}

__device__ __forceinline__ float tanh_f(float x) {
    float ax = fabsf(x);
    float e  = __expf(2.0f * ax);
    float r  = __fdividef(2.0f, e + 1.0f);
    return copysignf(1.0f - r, x);
}
__device__ __forceinline__ uint32_t bpack(float a, float b) {
    __nv_bfloat162 h = __floats2bfloat162_rn(a, b);
    return *(uint32_t*)&h;
}
__device__ __forceinline__ void writeA(uint32_t sb, int buf, int row, int col,
                                       float a, float b) {
    float ah = __bfloat162float(__float2bfloat16(a));
    float bh = __bfloat162float(__float2bfloat16(b));
    uint32_t off = sb + (uint32_t)buf * ABUF_B + (uint32_t)(row * LDA + col) * 2;
    asm volatile("st.shared.b32 [%0], %1;" :: "r"(off), "r"(bpack(ah, bh)) : "memory");
    asm volatile("st.shared.b32 [%0], %1;" :: "r"(off + A_LO), "r"(bpack(a - ah, b - bh)) : "memory");
}
__device__ __forceinline__ void sts_f4(uint32_t addr, float4 v) {
    asm volatile("st.shared.v4.b32 [%0], {%1,%2,%3,%4};"
                 :: "r"(addr), "r"(__float_as_uint(v.x)), "r"(__float_as_uint(v.y)),
                    "r"(__float_as_uint(v.z)), "r"(__float_as_uint(v.w)) : "memory");
}
__device__ __forceinline__ float4 lds_f4(uint32_t addr) {
    uint32_t a, b, c, d;
    asm volatile("ld.shared.v4.b32 {%0,%1,%2,%3}, [%4];"
                 : "=r"(a), "=r"(b), "=r"(c), "=r"(d) : "r"(addr));
    return make_float4(__uint_as_float(a), __uint_as_float(b),
                       __uint_as_float(c), __uint_as_float(d));
}

// ---------------------------------------------------------------------------
// prep: W -> fragment-order image. For (combo, h, lane, rr):
//   reg r = h*4+rr; frag f = r>>1; within-frag reg = r&1.
//   n = ns*32 + f*8 + lane/4;  k = sub*32 + kq*16 + (r&1)*8 + 2*(lane&3).
//   value pair = { B[n][k], B[n][k+1] } = { W[k][n], W[k+1][n] }, hi/lo plane.
// ---------------------------------------------------------------------------
__global__ void prep_kernel(const float* __restrict__ W1, const float* __restrict__ W2) {
    int i = blockIdx.x * blockDim.x + threadIdx.x;   // 0..131071
    int rr = i & 3, lane = (i >> 2) & 31, h = (i >> 7) & 1;
    int plane = (i >> 8) & 1, kq = (i >> 9) & 1, sub = (i >> 10) & 7;
    int ns = (i >> 13) & 7, wi = (i >> 16) & 1;
    int r = h * 4 + rr, f = r >> 1;
    int n = ns * 32 + f * 8 + (lane >> 2);
    int k = sub * 32 + kq * 16 + (r & 1) * 8 + 2 * (lane & 3);
    const float* W = wi ? W2 : W1;
    float v0 = W[k * 256 + n], v1 = W[(k + 1) * 256 + n];
    __nv_bfloat16 h0 = __float2bfloat16(v0), h1 = __float2bfloat16(v1);
    uint32_t outv;
    if (plane == 0) {
        outv = ((uint32_t)__bfloat16_as_ushort(h1) << 16) | __bfloat16_as_ushort(h0);
    } else {
        __nv_bfloat16 l0 = __float2bfloat16(v0 - __bfloat162float(h0));
        __nv_bfloat16 l1 = __float2bfloat16(v1 - __bfloat162float(h1));
        outv = ((uint32_t)__bfloat16_as_ushort(l1) << 16) | __bfloat16_as_ushort(l0);
    }
    // store at combo*256 + (plane folded in combo) ... linear uint32 index:
    // ((combo)*2 + h)*... layout: combo has 64 uint4 = 256 uint32:
    //   u32 index within combo = (h*32 + lane)*4 + rr
    int combo = ((((wi * 8 + ns) * 8 + sub) * 2 + kq) * 2 + plane);
    g_wfrag[combo * 256 + (h * 32 + lane) * 4 + rr] = outv;
}

// load this warp's B frags for one k16-step: hi[0..7] + lo[0..7] (16 regs)
__device__ __forceinline__ void ldw(int wi, int sub, int kq, int ns, int lane,
                                    uint32_t* dst) {
    const uint4* p = (const uint4*)g_wfrag +
                     (size_t)((((wi * 8 + ns) * 8 + sub) * 2 + kq) * 2) * 64 + lane;
    uint4 t0 = p[0], t1 = p[32];     // plane 0 (hi): regs 0-3, 4-7
    uint4 t2 = p[64], t3 = p[96];    // plane 1 (lo)
    dst[0] = t0.x; dst[1] = t0.y; dst[2]  = t0.z; dst[3]  = t0.w;
    dst[4] = t1.x; dst[5] = t1.y; dst[6]  = t1.z; dst[7]  = t1.w;
    dst[8] = t2.x; dst[9] = t2.y; dst[10] = t2.z; dst[11] = t2.w;
    dst[12] = t3.x; dst[13] = t3.y; dst[14] = t3.z; dst[15] = t3.w;
}

__global__ void __launch_bounds__(THREADS, 2)
ode_hmma_kernel(const float* __restrict__ x0, float* __restrict__ out) {
    extern __shared__ __align__(16) char smem[];
    const uint32_t sb = smem_u32(smem);
    const int tid = threadIdx.x, warp = tid >> 5, lane = tid & 31;
    const int quad = lane >> 3, lrow = lane & 7;

    const int a_row  = lrow + ((quad & 1) << 3);     // m16
    const int a_col8 = (quad >> 1) << 3;

    const int erow = lane >> 2;                      // 0..7 (rows erow, erow+8)
    const int ecol = warp * 32 + 2 * (lane & 3);     // + ni*8, ni<4
    const int fbase = blockIdx.x * FRAG_CTA + warp * 512 + lane * 4;
    const int growb = blockIdx.x * M_CTA;
    const uint32_t xab = sb + XACC_OFF + (uint32_t)tid * 16;   // + ni*4096

    float4 xreg[4];

    // ---- init: x0 -> x regs and A buffer 0 ----
#pragma unroll
    for (int ni = 0; ni < 4; ni++) {
        int col = ecol + ni * 8;
        float2 v01 = *(const float2*)&x0[(growb + erow) * DIM + col];
        float2 v23 = *(const float2*)&x0[(growb + erow + 8) * DIM + col];
        xreg[ni] = make_float4(v01.x, v01.y, v23.x, v23.y);
        writeA(sb, 0, erow, col, v01.x, v01.y);
        writeA(sb, 0, erow + 8, col, v23.x, v23.y);
    }

    uint32_t bw[2][16];
    ldw(0, 0, 0, warp, lane, bw[0]);   // k-step 0

    __syncthreads();

    float accA[4][4], accB[4][4];
#pragma unroll 1
    for (int g = 0; g < NGEMM; g++) {
        const int s = (g >> 1) % 6, j = g & 1;
        const uint32_t abase = sb + (uint32_t)(g & 1) * ABUF_B;
#pragma unroll
        for (int ni = 0; ni < 4; ni++)
#pragma unroll
            for (int c = 0; c < 4; c++) {
                accA[ni][c] = 0.0f;
                accB[ni][c] = 0.0f;
            }

#pragma unroll 2
        for (int ks = 0; ks < 16; ks++) {          // 16 k16-steps per GEMM
            const int step = g * 16 + ks;
            if (step + 1 < NKSTEP) {               // prefetch next step's B
                const int sn = step + 1;
                ldw((sn >> 4) & 1, (sn >> 1) & 7, sn & 1, warp, lane, bw[sn & 1]);
            }
            const uint32_t* bb = bw[step & 1];
            const uint32_t* bhi = bb;
            const uint32_t* blo = bb + 8;
            uint32_t ahi[4], alo[4];
            uint32_t ao = abase + (uint32_t)((a_row * LDA + ks * 16 + a_col8) * 2);
            ldsm_x4(ahi, ao);
            ldsm_x4(alo, ao + A_LO);
#pragma unroll
            for (int ni = 0; ni < 4; ni++) {
                mma_bf16(accA[ni], ahi, &bhi[ni * 2]);  // hi*hi
                mma_bf16(accB[ni], alo, &bhi[ni * 2]);  // lo*hi
                mma_bf16(accB[ni], ahi, &blo[ni * 2]);  // hi*lo
            }
        }

        // ---- epilogue -> A buffer (g+1)&1 ----
        const int nbuf = (g + 1) & 1;
        if (j == 0) {                      // h = tanh(x@W1)
#pragma unroll
            for (int ni = 0; ni < 4; ni++) {
                float a0 = accA[ni][0] + accB[ni][0];
                float a1 = accA[ni][1] + accB[ni][1];
                float a2 = accA[ni][2] + accB[ni][2];
                float a3 = accA[ni][3] + accB[ni][3];
                int col = ecol + ni * 8;
                writeA(sb, nbuf, erow, col, tanh_f(a0), tanh_f(a1));
                writeA(sb, nbuf, erow + 8, col, tanh_f(a2), tanh_f(a3));
            }
        } else {                           // k_{s+1} = h@W2; RK update
            const bool fin = (s == 5);
            const float cc = c_cur[s];
            const float cb = c_b[s];
#pragma unroll
            for (int ni = 0; ni < 4; ni++) {
                const int fi = fbase + ni * 128;
                const uint32_t xaddr = xab + (uint32_t)ni * 4096;
                float4 kc = make_float4(accA[ni][0] + accB[ni][0],
                                        accA[ni][1] + accB[ni][1],
                                        accA[ni][2] + accB[ni][2],
                                        accA[ni][3] + accB[ni][3]);
                if (s <= 3) *(float4*)&g_k[s][fi] = kc;
                float4 xv = xreg[ni];
                if (s == 0) {
                    sts_f4(xaddr, make_float4(fmaf(cb, kc.x, xv.x), fmaf(cb, kc.y, xv.y),
                                              fmaf(cb, kc.z, xv.z), fmaf(cb, kc.w, xv.w)));
                } else if (cb != 0.0f) {
                    float4 t = lds_f4(xaddr);
                    sts_f4(xaddr, make_float4(fmaf(cb, kc.x, t.x), fmaf(cb, kc.y, t.y),
                                              fmaf(cb, kc.z, t.z), fmaf(cb, kc.w, t.w)));
                }
                float4 na;
                if (!fin) {                // y_{s+2} = x + cc*k_cur + sum_{sl<s}
                    na = make_float4(fmaf(cc, kc.x, xv.x), fmaf(cc, kc.y, xv.y),
                                     fmaf(cc, kc.z, xv.z), fmaf(cc, kc.w, xv.w));
                    float4 kv[4];
#pragma unroll
                    for (int sl = 0; sl < 4; sl++)
                        if (sl < s) kv[sl] = *(const float4*)&g_k[sl][fi];
#pragma unroll
                    for (int sl = 0; sl < 4; sl++)
                        if (sl < s) {
                            float cf = c_slot[s][sl];
                            na.x = fmaf(cf, kv[sl].x, na.x);
                            na.y = fmaf(cf, kv[sl].y, na.y);
                            na.z = fmaf(cf, kv[sl].z, na.z);
                            na.w = fmaf(cf, kv[sl].w, na.w);
                        }
                } else {                   // new x = xacc + h*b6*k6
                    float4 t = lds_f4(xaddr);
                    na = make_float4(fmaf(cc, kc.x, t.x), fmaf(cc, kc.y, t.y),
                                     fmaf(cc, kc.z, t.z), fmaf(cc, kc.w, t.w));
                    xreg[ni] = na;
                }
                int col = ecol + ni * 8;
                if (g == NGEMM - 1) {
                    *(float2*)&out[(growb + erow) * DIM + col] = make_float2(na.x, na.y);
                    *(float2*)&out[(growb + erow + 8) * DIM + col] = make_float2(na.z, na.w);
                } else {
                    writeA(sb, nbuf, erow, col, na.x, na.y);
                    writeA(sb, nbuf, erow + 8, col, na.z, na.w);
                }
            }
        }
        __syncthreads();   // publish A buffer (g+1)&1
    }
}

extern "C" void kernel_launch(void* const* d_in, const int* in_sizes, int n_in,
                              void* d_out, int out_size) {
    (void)in_sizes; (void)n_in; (void)out_size;
    const float* x0 = (const float*)d_in[0];
    const float* W1 = (const float*)d_in[1];
    const float* W2 = (const float*)d_in[2];
    float* out = (float*)d_out;

    prep_kernel<<<512, 256>>>(W1, W2);
    cudaFuncSetAttribute(ode_hmma_kernel,
                         cudaFuncAttributeMaxDynamicSharedMemorySize, SMEM_BYTES);
    ode_hmma_kernel<<<NCTA, THREADS, SMEM_BYTES>>>(x0, out);
}